// round 1
// baseline (speedup 1.0000x reference)
#include <cuda_runtime.h>

// Problem constants (from reference): B=4096 chains, T=4096 steps, NF=1, H=1.
#define BATCH 4096
#define SEQ   4096

static __device__ __forceinline__ float ex2f_(float x) {
    float y; asm("ex2.approx.f32 %0, %1;" : "=f"(y) : "f"(x)); return y;
}
static __device__ __forceinline__ float rcpf_(float x) {
    float y; asm("rcp.approx.f32 %0, %1;" : "=f"(y) : "f"(x)); return y;
}

// One thread = one batch row = one fully serial GRU chain of SEQ steps.
// Latency-bound: per-step critical path ~96 cycles (2 serial sigmoid/tanh
// chains of FMA->EX2->FADD->RCP). Everything else (input proj, z-gate,
// output tanh, loads, stores) sits off the recurrence path.
__global__ void __launch_bounds__(32) gru_scan_kernel(
    const float* __restrict__ xi,    // (B, T, 2): [x, label] interleaved
    const float* __restrict__ Wih,   // (3, 2) rows: r, z, n
    const float* __restrict__ Whh,   // (3, 1)
    const float* __restrict__ bih,   // (3,)
    const float* __restrict__ bhh,   // (3,)
    float* __restrict__ out,         // (B, T) tanh(h)
    float* __restrict__ outl)        // (B, T) labels copy, or nullptr
{
    const int b = blockIdx.x * 32 + threadIdx.x;
    const float L2E = 1.44269504088896340736f;

    const size_t rowoff = (size_t)b * (SEQ * 2);
    const float4* __restrict__ xrow = (const float4*)(xi + rowoff);
    const float label = xi[rowoff + 1];

    // Weights (broadcast loads; L2-resident after first warp)
    const float Ar = Wih[0], Br = Wih[1];
    const float Az = Wih[2], Bz = Wih[3];
    const float An = Wih[4], Bn = Wih[5];
    const float Wr = Whh[0], Wz = Whh[1], Wn = Whh[2];

    // Fold label channel, biases, and log2(e) scaling into constants so the
    // exp2 argument is produced by bare FMAs:
    //   sigmoid(a) = rcp(1 + exp2(-L2E * a))
    //   tanh(a)    = 2 * rcp(1 + exp2(-2*L2E * a)) - 1
    const float arx = -L2E * Ar;
    const float wrx = -L2E * Wr;
    const float crx = -L2E * (Br * label + bih[0] + bhh[0]);
    const float azx = -L2E * Az;
    const float wzx = -L2E * Wz;
    const float czx = -L2E * (Bz * label + bih[1] + bhh[1]);
    const float anx = -2.0f * L2E * An;
    const float cnx = -2.0f * L2E * (Bn * label + bih[2]);
    const float wnx = -2.0f * L2E * Wn;
    const float bnx = -2.0f * L2E * bhh[2];

    float h = 0.0f;
    float4* __restrict__ orow = (float4*)(out + (size_t)b * SEQ);
    float4* __restrict__ lrow = outl ? (float4*)(outl + (size_t)b * SEQ) : (float4*)0;
    const float4 lab4 = make_float4(label, label, label, label);

    // Double-buffered 8-step chunks: 4x LDG.128 per chunk (64B contiguous),
    // issued one full chunk (~800 cyc) ahead of use -> DRAM latency hidden.
    float4 A0 = xrow[0], A1 = xrow[1], A2 = xrow[2], A3 = xrow[3];
    float4 B0, B1, B2, B3;

#define STEP(xv, dst) do {                                   \
        float x_     = (xv);                                 \
        float pre_r  = fmaf(arx, x_, crx);                   \
        float pre_z  = fmaf(azx, x_, czx);                   \
        float base_n = fmaf(anx, x_, cnx);                   \
        float hn_s   = fmaf(wnx, h, bnx);                    \
        float s_r    = fmaf(wrx, h, pre_r);                  \
        float s_z    = fmaf(wzx, h, pre_z);                  \
        float r_     = rcpf_(1.0f + ex2f_(s_r));             \
        float z_     = rcpf_(1.0f + ex2f_(s_z));             \
        float s_n    = fmaf(r_, hn_s, base_n);               \
        float n_     = fmaf(2.0f, rcpf_(1.0f + ex2f_(s_n)), -1.0f); \
        h            = fmaf(z_, h - n_, n_);                 \
        float sy     = h * (-2.0f * L2E);                    \
        (dst)        = fmaf(2.0f, rcpf_(1.0f + ex2f_(sy)), -1.0f);  \
    } while (0)

#define CHUNK(C0, C1, C2, C3, c) do {                        \
        float4 y0, y1;                                       \
        STEP((C0).x, y0.x); STEP((C0).z, y0.y);              \
        STEP((C1).x, y0.z); STEP((C1).z, y0.w);              \
        STEP((C2).x, y1.x); STEP((C2).z, y1.y);              \
        STEP((C3).x, y1.z); STEP((C3).z, y1.w);              \
        orow[(c) * 2]     = y0;                              \
        orow[(c) * 2 + 1] = y1;                              \
        if (lrow) { lrow[(c) * 2] = lab4; lrow[(c) * 2 + 1] = lab4; } \
    } while (0)

    const int NCH = SEQ / 8;  // 512 chunks, even
    for (int c = 0; c < NCH; c += 2) {
        B0 = xrow[(c + 1) * 4 + 0];
        B1 = xrow[(c + 1) * 4 + 1];
        B2 = xrow[(c + 1) * 4 + 2];
        B3 = xrow[(c + 1) * 4 + 3];
        CHUNK(A0, A1, A2, A3, c);
        if (c + 2 < NCH) {
            A0 = xrow[(c + 2) * 4 + 0];
            A1 = xrow[(c + 2) * 4 + 1];
            A2 = xrow[(c + 2) * 4 + 2];
            A3 = xrow[(c + 2) * 4 + 3];
        }
        CHUNK(B0, B1, B2, B3, c + 1);
    }
#undef CHUNK
#undef STEP
}

extern "C" void kernel_launch(void* const* d_in, const int* in_sizes, int n_in,
                              void* d_out, int out_size)
{
    // metadata order: xi, labels, Wih, Whh, bih, bhh, size, batch, nC
    const float* xi  = (const float*)d_in[0];
    const float* Wih = (const float*)d_in[2];
    const float* Whh = (const float*)d_in[3];
    const float* bih = (const float*)d_in[4];
    const float* bhh = (const float*)d_in[5];

    float* out = (float*)d_out;
    // Tuple output (tanh(out), labels): write the labels half only if the
    // harness materialized it.
    float* outl = (out_size >= 2 * BATCH * SEQ) ? (out + (size_t)BATCH * SEQ)
                                                : (float*)0;

    // 128 blocks x 32 threads: one warp per SM -> each serial chain gets a
    // private SMSP (scheduler + MUFU pipe); this kernel is pure latency.
    gru_scan_kernel<<<BATCH / 32, 32>>>(xi, Wih, Whh, bih, bhh, out, outl);
}

// round 2
// speedup vs baseline: 1.2198x; 1.2198x over previous
#include <cuda_runtime.h>

#define BATCH 4096
#define SEQ   4096
#define BT    (BATCH * SEQ)

static __device__ __forceinline__ float ex2f_(float x) {
    float y; asm("ex2.approx.f32 %0, %1;" : "=f"(y) : "f"(x)); return y;
}
static __device__ __forceinline__ float rcpf_(float x) {
    float y; asm("rcp.approx.f32 %0, %1;" : "=f"(y) : "f"(x)); return y;
}
static __device__ __forceinline__ float tanhf_(float x) {
    float y; asm("tanh.approx.f32 %0, %1;" : "=f"(y) : "f"(x)); return y;
}

// ---------------------------------------------------------------------------
// Scan kernel: one thread = one chain of SEQ serial GRU steps. Stores RAW h.
// Serial per-step path (target):
//   h -> FMA(s_r) -> TANH(r) -> FMA(s_n) -> EX2 -> FADD -> RCP -> FMA(n)
//     -> FSUB -> FMA(h')                                  ~72 cyc ideal
// z-gate (FMA+TANH+FMA) and all x-projections are off-path.
// ---------------------------------------------------------------------------
__global__ void __launch_bounds__(32) gru_scan_kernel(
    const float* __restrict__ xi,    // (B, T, 2): [x, label]
    const float* __restrict__ Wih,   // (3,2) rows r,z,n
    const float* __restrict__ Whh,   // (3,)
    const float* __restrict__ bih,   // (3,)
    const float* __restrict__ bhh,   // (3,)
    float* __restrict__ hraw)        // (B, T) raw h
{
    const int b = blockIdx.x * 32 + threadIdx.x;
    const float L2E = 1.44269504088896340736f;
    const float S   = -2.0f * L2E;   // tanh(a) = 2*rcp(1+exp2(S*a)) - 1

    const size_t rowoff = (size_t)b * (SEQ * 2);
    const float4* __restrict__ xrow = (const float4*)(xi + rowoff);
    const float label = xi[rowoff + 1];

    const float Ar = Wih[0], Br = Wih[1];
    const float Az = Wih[2], Bz = Wih[3];
    const float An = Wih[4], Bn = Wih[5];
    const float Wr = Whh[0], Wz = Whh[1], Wn = Whh[2];

    // r,z as sigmoid via MUFU.TANH:  sig(v) = 0.5*tanh(v/2) + 0.5
    const float ar2 = 0.5f * Ar, wr2 = 0.5f * Wr;
    const float cr2 = 0.5f * (Br * label + bih[0] + bhh[0]);
    const float az2 = 0.5f * Az, wz2 = 0.5f * Wz;
    const float cz2 = 0.5f * (Bz * label + bih[1] + bhh[1]);
    // n accurate: s_n = S*(inn + r*hn); Shn = S*Wn*h + S*bhh_n
    const float anS = S * An;
    const float cnS = S * (Bn * label + bih[2]);
    const float wnS = S * Wn, bnS = S * bhh[2];

    float h = 0.0f;
    float4* __restrict__ orow = (float4*)(hraw + (size_t)b * SEQ);

    float4 A0 = xrow[0], A1 = xrow[1], A2 = xrow[2], A3 = xrow[3];
    float4 B0, B1, B2, B3;

#define STEP(prr, prz, pbn, dst) do {                                  \
        float s_r   = fmaf(wr2, h, (prr));                             \
        float s_z   = fmaf(wz2, h, (prz));                             \
        float Shn   = fmaf(wnS, h, bnS);                               \
        float tr    = tanhf_(s_r);                                     \
        float tz    = tanhf_(s_z);                                     \
        float hShn  = 0.5f * Shn;                                      \
        float c2    = fmaf(0.5f, Shn, (pbn));                          \
        float s_n   = fmaf(tr, hShn, c2);                              \
        float q     = rcpf_(1.0f + ex2f_(s_n));                        \
        float n_    = fmaf(2.0f, q, -1.0f);                            \
        float zf    = fmaf(0.5f, tz, 0.5f);                            \
        h           = fmaf(zf, h - n_, n_);                            \
        (dst)       = h;                                               \
    } while (0)

#define CHUNK(C0, C1, C2, C3, c) do {                                  \
        /* x-only projections: independent of h, computed up front */  \
        float pr0 = fmaf(ar2, (C0).x, cr2), pz0 = fmaf(az2, (C0).x, cz2), pn0 = fmaf(anS, (C0).x, cnS); \
        float pr1 = fmaf(ar2, (C0).z, cr2), pz1 = fmaf(az2, (C0).z, cz2), pn1 = fmaf(anS, (C0).z, cnS); \
        float pr2 = fmaf(ar2, (C1).x, cr2), pz2 = fmaf(az2, (C1).x, cz2), pn2 = fmaf(anS, (C1).x, cnS); \
        float pr3 = fmaf(ar2, (C1).z, cr2), pz3 = fmaf(az2, (C1).z, cz2), pn3 = fmaf(anS, (C1).z, cnS); \
        float pr4 = fmaf(ar2, (C2).x, cr2), pz4 = fmaf(az2, (C2).x, cz2), pn4 = fmaf(anS, (C2).x, cnS); \
        float pr5 = fmaf(ar2, (C2).z, cr2), pz5 = fmaf(az2, (C2).z, cz2), pn5 = fmaf(anS, (C2).z, cnS); \
        float pr6 = fmaf(ar2, (C3).x, cr2), pz6 = fmaf(az2, (C3).x, cz2), pn6 = fmaf(anS, (C3).x, cnS); \
        float pr7 = fmaf(ar2, (C3).z, cr2), pz7 = fmaf(az2, (C3).z, cz2), pn7 = fmaf(anS, (C3).z, cnS); \
        float4 y0, y1;                                                 \
        STEP(pr0, pz0, pn0, y0.x); STEP(pr1, pz1, pn1, y0.y);          \
        STEP(pr2, pz2, pn2, y0.z); STEP(pr3, pz3, pn3, y0.w);          \
        STEP(pr4, pz4, pn4, y1.x); STEP(pr5, pz5, pn5, y1.y);          \
        STEP(pr6, pz6, pn6, y1.z); STEP(pr7, pz7, pn7, y1.w);          \
        orow[(c) * 2]     = y0;                                        \
        orow[(c) * 2 + 1] = y1;                                        \
    } while (0)

    const int NCH = SEQ / 8;
    for (int c = 0; c < NCH; c += 2) {
        B0 = xrow[(c + 1) * 4 + 0];
        B1 = xrow[(c + 1) * 4 + 1];
        B2 = xrow[(c + 1) * 4 + 2];
        B3 = xrow[(c + 1) * 4 + 3];
        CHUNK(A0, A1, A2, A3, c);
        if (c + 2 < NCH) {
            A0 = xrow[(c + 2) * 4 + 0];
            A1 = xrow[(c + 2) * 4 + 1];
            A2 = xrow[(c + 2) * 4 + 2];
            A3 = xrow[(c + 2) * 4 + 3];
        }
        CHUNK(B0, B1, B2, B3, c + 1);
    }
#undef CHUNK
#undef STEP
}

// ---------------------------------------------------------------------------
// Finish kernel: fully parallel. In-place accurate tanh on the raw h half,
// plus labels copy into the second half (if materialized).
// ---------------------------------------------------------------------------
__global__ void finish_kernel(float4* __restrict__ out,         // BT/4 elems
                              const float4* __restrict__ labels,
                              float4* __restrict__ outl)        // or nullptr
{
    const float S = -2.0f * 1.44269504088896340736f;
    int i = blockIdx.x * blockDim.x + threadIdx.x;
    float4 v = out[i];
    v.x = fmaf(2.0f, rcpf_(1.0f + ex2f_(S * v.x)), -1.0f);
    v.y = fmaf(2.0f, rcpf_(1.0f + ex2f_(S * v.y)), -1.0f);
    v.z = fmaf(2.0f, rcpf_(1.0f + ex2f_(S * v.z)), -1.0f);
    v.w = fmaf(2.0f, rcpf_(1.0f + ex2f_(S * v.w)), -1.0f);
    out[i] = v;
    if (outl) outl[i] = labels[i];
}

extern "C" void kernel_launch(void* const* d_in, const int* in_sizes, int n_in,
                              void* d_out, int out_size)
{
    const float* xi     = (const float*)d_in[0];
    const float* labels = (const float*)d_in[1];
    const float* Wih    = (const float*)d_in[2];
    const float* Whh    = (const float*)d_in[3];
    const float* bih    = (const float*)d_in[4];
    const float* bhh    = (const float*)d_in[5];

    float* out  = (float*)d_out;
    float* outl = (out_size >= 2 * BT) ? (out + (size_t)BT) : (float*)0;

    // Phase 1: serial scans, raw h into the first half of d_out.
    gru_scan_kernel<<<BATCH / 32, 32>>>(xi, Wih, Whh, bih, bhh, out);

    // Phase 2: elementwise tanh in place + labels copy, fully parallel.
    const int N4 = BT / 4;
    finish_kernel<<<N4 / 256, 256>>>((float4*)out, (const float4*)labels,
                                     (float4*)outl);
}